// round 15
// baseline (speedup 1.0000x reference)
#include <cuda_runtime.h>
#include <cstdint>

#define T_STEPS 512
#define BATCH   256
#define HID     256
#define G3      768   // 3*HID

#define J_TILE  32    // hidden units per block (96 gate rows)
#define B_TILE  16    // batch rows per group
#define NGRP    16    // batch groups (= clusters)
#define NJT     8     // j-tiles (= cluster size)
#define CHUNK   64    // steps per launch

// ---------------- static scratch (no allocations allowed) ----------------
__device__ float g_gi[(size_t)T_STEPS * G3 * BATCH];    // [t][g][b]
__device__ float g_hs[(size_t)T_STEPS * BATCH * HID];   // [t][b][j]

// ---------------- helpers ----------------
__device__ __forceinline__ void ffma2(unsigned long long& d,
                                      unsigned long long a,
                                      unsigned long long b) {
    asm("fma.rn.f32x2 %0, %1, %2, %0;" : "+l"(d) : "l"(a), "l"(b));
}
__device__ __forceinline__ unsigned long long pk2(float s) {
    unsigned long long d;
    asm("mov.b64 %0, {%1,%1};" : "=l"(d) : "f"(s));
    return d;
}
__device__ __forceinline__ float2 upk(unsigned long long v) {
    float2 f;
    asm("mov.b64 {%0,%1}, %2;" : "=f"(f.x), "=f"(f.y) : "l"(v));
    return f;
}
__device__ __forceinline__ float sigm(float x) {
    return 1.0f / (1.0f + __expf(-x));
}
__device__ __forceinline__ float fast_tanh(float x) {
    float e = __expf(2.0f * x);
    return 1.0f - __fdividef(2.0f, e + 1.0f);
}

// mbarrier: local wait (acquire, cluster scope)
__device__ __forceinline__ void mbar_wait_acq_cluster(uint32_t addr, unsigned parity) {
    unsigned done;
    do {
        asm volatile(
            "{\n\t.reg .pred p;\n\t"
            "mbarrier.try_wait.parity.acquire.cluster.shared::cta.b64 p, [%1], %2, 0x989680;\n\t"
            "selp.b32 %0, 1, 0, p;\n\t}"
            : "=r"(done) : "r"(addr), "r"(parity) : "memory");
    } while (!done);
}
// mbarrier: remote arrive (release, cluster scope) on cluster rank's barrier
__device__ __forceinline__ void mbar_arrive_rel_cluster(uint32_t local_addr, unsigned rank) {
    asm volatile(
        "{\n\t.reg .b32 ra;\n\t"
        "mapa.shared::cluster.u32 ra, %0, %1;\n\t"
        "mbarrier.arrive.release.cluster.shared::cluster.b64 _, [ra];\n\t}"
        :: "r"(local_addr), "r"(rank) : "memory");
}

// ---------------- phase 0: gi[t][g][b] = sum_i w_ih[g][i]*x[b][t][i] + b_ih[g] ----------------
__global__ void __launch_bounds__(256) input_proj_kernel(
    const float* __restrict__ x, const float* __restrict__ w_ih,
    const float* __restrict__ b_ih) {
    extern __shared__ float sm[];
    float* wsm = sm;              // wsm[i*132 + g_local]
    float* xsm = sm + 64 * 132;   // xsm[i*132 + b_local]

    const int t  = blockIdx.x;
    const int g0 = blockIdx.y * 128;
    const int b0 = blockIdx.z * 128;
    const int tid = threadIdx.x;

#pragma unroll
    for (int it = 0; it < 8; it++) {
        int f  = tid + 256 * it;
        int gg = f >> 4, i4 = f & 15;
        float4 v = *(const float4*)(w_ih + (size_t)(g0 + gg) * 64 + i4 * 4);
        wsm[(i4 * 4 + 0) * 132 + gg] = v.x;
        wsm[(i4 * 4 + 1) * 132 + gg] = v.y;
        wsm[(i4 * 4 + 2) * 132 + gg] = v.z;
        wsm[(i4 * 4 + 3) * 132 + gg] = v.w;
    }
#pragma unroll
    for (int it = 0; it < 8; it++) {
        int f  = tid + 256 * it;
        int bb = f >> 4, i4 = f & 15;
        float4 v = *(const float4*)(x + ((size_t)(b0 + bb) * T_STEPS + t) * 64 + i4 * 4);
        xsm[(i4 * 4 + 0) * 132 + bb] = v.x;
        xsm[(i4 * 4 + 1) * 132 + bb] = v.y;
        xsm[(i4 * 4 + 2) * 132 + bb] = v.z;
        xsm[(i4 * 4 + 3) * 132 + bb] = v.w;
    }
    __syncthreads();

    const int tg = tid & 15, tb = tid >> 4;
    const int gl = tg * 8, bl = tb * 8;

    unsigned long long acc[32];
#pragma unroll
    for (int i = 0; i < 32; i++) acc[i] = 0ULL;

#pragma unroll 2
    for (int k = 0; k < 64; k++) {
        float4 wa = *(const float4*)(wsm + k * 132 + gl);
        float4 wb = *(const float4*)(wsm + k * 132 + gl + 4);
        ulonglong2 x01 = *(const ulonglong2*)(xsm + k * 132 + bl);
        ulonglong2 x23 = *(const ulonglong2*)(xsm + k * 132 + bl + 4);
        float wr[8] = {wa.x, wa.y, wa.z, wa.w, wb.x, wb.y, wb.z, wb.w};
#pragma unroll
        for (int gg = 0; gg < 8; gg++) {
            unsigned long long wd = pk2(wr[gg]);
            ffma2(acc[gg * 4 + 0], wd, x01.x);
            ffma2(acc[gg * 4 + 1], wd, x01.y);
            ffma2(acc[gg * 4 + 2], wd, x23.x);
            ffma2(acc[gg * 4 + 3], wd, x23.y);
        }
    }

#pragma unroll
    for (int gg = 0; gg < 8; gg++) {
        float bias = __ldg(b_ih + g0 + gl + gg);
        float2 p0 = upk(acc[gg * 4 + 0]);
        float2 p1 = upk(acc[gg * 4 + 1]);
        float2 p2 = upk(acc[gg * 4 + 2]);
        float2 p3 = upk(acc[gg * 4 + 3]);
        float* o = g_gi + ((size_t)t * G3 + (g0 + gl + gg)) * BATCH + b0 + bl;
        *(float4*)o       = make_float4(p0.x + bias, p0.y + bias, p1.x + bias, p1.y + bias);
        *(float4*)(o + 4) = make_float4(p2.x + bias, p2.y + bias, p3.x + bias, p3.y + bias);
    }
}

// ---------------- phase 1: GRU recurrence, mbarrier-cluster sync ----------------
// grid (8 jt, 16 grp), cluster (8,1,1) = the 8 j-tiles of one batch group.
// block 256 = (rg 0..15)x(bg 0..1)x(kc 0..7). j-tile 32 (96 rows), b-tile 16.
// Data via L2 (g_hs); sync via ping-pong SMEM mbarriers (8 arrivals each):
// producer combine -> stcg h -> syncthreads -> 8x mbarrier.arrive.release.cluster;
// consumer waits on ITS OWN mbarrier (acquire.cluster, HW sleep) then fills.
// No threadfence, no global counter, no L2 polling, no barrier.cluster per step.
#define HSTRIDE 260
#define RPITCH  20

__global__ void __launch_bounds__(256) __cluster_dims__(NJT, 1, 1)
gru_rec_kernel(const float* __restrict__ w_hh, const float* __restrict__ b_hh,
               int chunk) {
    extern __shared__ float sm[];
    float* w_il  = sm;                       // [96][256]   96 KB
    float* h_s   = sm + 96 * 256;            // [16][260]   16.6 KB
    float* red_s = h_s + 16 * HSTRIDE;       // [96][20]    7.5 KB
    __shared__ __align__(8) unsigned long long s_mbar[2];

    const int tid = threadIdx.x;
    const int rg  = tid >> 4;                // 0..15 row group (6 rows)
    const int bg  = (tid >> 3) & 1;          // batch parity
    const int kc  = tid & 7;                 // k chunk
    const int jt  = blockIdx.x;              // 0..7 (= cluster rank)
    const int grp = blockIdx.y;              // 0..15
    const int b0  = grp * B_TILE;
    const int j0  = jt * J_TILE;

    const uint32_t mb0 = (uint32_t)__cvta_generic_to_shared(&s_mbar[0]);
    if (tid == 0) {
        asm volatile("mbarrier.init.shared.b64 [%0], %1;" :: "r"(mb0), "r"(8u) : "memory");
        asm volatile("mbarrier.init.shared.b64 [%0], %1;" :: "r"(mb0 + 8), "r"(8u) : "memory");
    }

    // ---- preload weights: w_il[row][k], row = jloc*3 + gate (96 rows) ----
#pragma unroll
    for (int it = 0; it < 24; it++) {
        int f4 = tid + 256 * it;             // 0..6143 float4 slots
        int row = f4 >> 6, k4 = f4 & 63;
        int jloc = row / 3, g = row - 3 * jloc;
        float4 v = __ldg((const float4*)(w_hh +
                     ((size_t)(g * 256 + j0 + jloc)) * 256 + k4 * 4));
        *(float4*)(w_il + row * 256 + k4 * 4) = v;
    }
    __syncthreads();
    // all peers' mbarriers must be initialized before any arrive lands
    asm volatile("barrier.cluster.arrive.aligned;" ::: "memory");
    asm volatile("barrier.cluster.wait.aligned;" ::: "memory");

    // combine-role constants (tid < 128): jloc = tid&31, bq = tid>>5 (0..3)
    const int c_jl = tid & 31;
    const int c_bq = tid >> 5;
    const int c_j  = j0 + c_jl;
    const int qq   = c_jl >> 2;              // 4x4 transpose group
    const int rr   = c_jl & 3;
    float br = 0.f, bz = 0.f, bn = 0.f;
    if (tid < 128) {
        br = __ldg(b_hh + c_j);
        bz = __ldg(b_hh + 256 + c_j);
        bn = __ldg(b_hh + 512 + c_j);
    }

    const int frow = tid & 15;               // fill: batch row
    const int fq   = tid >> 4;               // fill: 4-float4 group (0..15)

    const int t0 = chunk * CHUNK;
    int ph0 = 0, ph1 = 0;                    // mbarrier phase parities

    // prefetch gi(t0)
    float4 gir, giz, gin;
    if (tid < 128) {
        const float* giB = g_gi + (size_t)t0 * G3 * BATCH;
        gir = __ldcs((const float4*)(giB + (size_t)c_j * BATCH + b0 + 4 * c_bq));
        giz = __ldcs((const float4*)(giB + (size_t)(256 + c_j) * BATCH + b0 + 4 * c_bq));
        gin = __ldcs((const float4*)(giB + (size_t)(512 + c_j) * BATCH + b0 + 4 * c_bq));
    }

    const float* wrow = w_il + (6 * rg) * 256;

    for (int tl = 0; tl < CHUNK; tl++) {
        const int t = t0 + tl;

        if (t > 0) {
            if (tl > 0) {
                // wait for all 8 producers' h(t-1) (local mbarrier, buffer (t-1)&1)
                const int buf = (t - 1) & 1;
                mbar_wait_acq_cluster(mb0 + 8 * buf, buf ? ph1 : ph0);
                if (buf) ph1 ^= 1; else ph0 ^= 1;
            }
            // ---- fill h_s[b][k] from g_hs[t-1]: 16 rows x 256 ----
            const float4* src = (const float4*)(g_hs +
                                ((size_t)(t - 1) * BATCH + b0 + frow) * HID) + fq * 4;
            float4 v[4];
#pragma unroll
            for (int kk = 0; kk < 4; kk++) v[kk] = __ldcg(src + kk);
#pragma unroll
            for (int kk = 0; kk < 4; kk++)
                *(float4*)(h_s + frow * HSTRIDE + fq * 16 + kk * 4) = v[kk];
            __syncthreads();

            // ---- GEMM: 6 rows x 8 batches x 32 k per thread ----
            unsigned long long acc[6][8];
#pragma unroll
            for (int r = 0; r < 6; r++)
#pragma unroll
                for (int m = 0; m < 8; m++) acc[r][m] = 0ULL;

#pragma unroll
            for (int i = 0; i < 8; i++) {
                const int k4 = kc + 8 * i;
                ulonglong2 wv[6];
#pragma unroll
                for (int r = 0; r < 6; r++)
                    wv[r] = *(const ulonglong2*)(wrow + r * 256 + k4 * 4);
#pragma unroll
                for (int m = 0; m < 8; m++) {
                    ulonglong2 hv = *(const ulonglong2*)
                        (h_s + (2 * m + bg) * HSTRIDE + k4 * 4);
#pragma unroll
                    for (int r = 0; r < 6; r++) {
                        ffma2(acc[r][m], wv[r].x, hv.x);
                        ffma2(acc[r][m], wv[r].y, hv.y);
                    }
                }
            }

            // ---- fold f32x2 + butterfly kc-reduction with redistribution ----
            float s0[6][8];
#pragma unroll
            for (int r = 0; r < 6; r++)
#pragma unroll
                for (int m = 0; m < 8; m++) {
                    float2 p = upk(acc[r][m]);
                    s0[r][m] = p.x + p.y;
                }
            float s1[6][4];
            {
                bool hi = kc & 1;
#pragma unroll
                for (int r = 0; r < 6; r++)
#pragma unroll
                    for (int q = 0; q < 4; q++) {
                        float mine   = hi ? s0[r][2 * q + 1] : s0[r][2 * q];
                        float theirs = hi ? s0[r][2 * q]     : s0[r][2 * q + 1];
                        s1[r][q] = mine + __shfl_xor_sync(0xffffffffu, theirs, 1);
                    }
            }
            float s1b[6][2];
            {
                bool hi = (kc >> 1) & 1;
#pragma unroll
                for (int r = 0; r < 6; r++)
#pragma unroll
                    for (int q = 0; q < 2; q++) {
                        float mine   = hi ? s1[r][2 * q + 1] : s1[r][2 * q];
                        float theirs = hi ? s1[r][2 * q]     : s1[r][2 * q + 1];
                        s1b[r][q] = mine + __shfl_xor_sync(0xffffffffu, theirs, 2);
                    }
            }
            float s2[6];
            {
                bool hi = (kc >> 2) & 1;
#pragma unroll
                for (int r = 0; r < 6; r++) {
                    float mine   = hi ? s1b[r][1] : s1b[r][0];
                    float theirs = hi ? s1b[r][0] : s1b[r][1];
                    s2[r] = mine + __shfl_xor_sync(0xffffffffu, theirs, 4);
                }
            }
            // handoff: red_s[row][bb], bb = 2*kc + bg
            float* rs = red_s + (2 * kc + bg);
#pragma unroll
            for (int r = 0; r < 6; r++)
                rs[(6 * rg + r) * RPITCH] = s2[r];
            __syncthreads();
        }

        // ---- combine (tid < 128): 1 j x 4 batches each ----
        if (tid < 128) {
            float4 sR = make_float4(0.f, 0.f, 0.f, 0.f);
            float4 sZ = sR, sN = sR;
            if (t > 0) {
                sR = *(const float4*)(red_s + (3 * c_jl + 0) * RPITCH + 4 * c_bq);
                sZ = *(const float4*)(red_s + (3 * c_jl + 1) * RPITCH + 4 * c_bq);
                sN = *(const float4*)(red_s + (3 * c_jl + 2) * RPITCH + 4 * c_bq);
            }
            float sRa[4] = {sR.x, sR.y, sR.z, sR.w};
            float sZa[4] = {sZ.x, sZ.y, sZ.z, sZ.w};
            float sNa[4] = {sN.x, sN.y, sN.z, sN.w};
            float giRv[4] = {gir.x, gir.y, gir.z, gir.w};
            float giZv[4] = {giz.x, giz.y, giz.z, giz.w};
            float giNv[4] = {gin.x, gin.y, gin.z, gin.w};

            float hnew[4];
#pragma unroll
            for (int m = 0; m < 4; m++) {
                float rgt = sigm(giRv[m] + sRa[m] + br);
                float zg = sigm(giZv[m] + sZa[m] + bz);
                float ng = fast_tanh(giNv[m] + rgt * (sNa[m] + bn));
                float hp_ = (t == 0) ? 0.0f
                          : h_s[(4 * c_bq + m) * HSTRIDE + c_j];
                hnew[m] = (1.0f - zg) * ng + zg * hp_;
            }

            // ---- 4x4 transpose within lane quads ----
            float T[4];
#pragma unroll
            for (int d = 0; d < 4; d++) {
                int gidx = (rr + d) & 3;
                float sv = hnew[(rr - d) & 3];
                float rv = __shfl_sync(0xffffffffu, sv, ((tid & 31) & 28) | gidx);
                T[gidx] = rv;
            }

            // h store: one 16B store (b = b0+4*c_bq+rr, j = j0+4*qq..)
            float* hsT = g_hs + ((size_t)t * BATCH + b0 + 4 * c_bq + rr) * HID;
            __stcg((float4*)(hsT + j0 + 4 * qq),
                   make_float4(T[0], T[1], T[2], T[3]));
        }

        if (tl + 1 < CHUNK) {
            // order combine stores before the release-arrives
            __syncthreads();
            if (tid < 8)
                mbar_arrive_rel_cluster(mb0 + 8 * (t & 1), (unsigned)tid);

            // prefetch next gi under the (next iteration's) wait
            if (tid < 128) {
                const float* giN = g_gi + (size_t)(t + 1) * G3 * BATCH;
                gir = __ldcs((const float4*)(giN + (size_t)c_j * BATCH + b0 + 4 * c_bq));
                giz = __ldcs((const float4*)(giN + (size_t)(256 + c_j) * BATCH + b0 + 4 * c_bq));
                gin = __ldcs((const float4*)(giN + (size_t)(512 + c_j) * BATCH + b0 + 4 * c_bq));
            }
        }
    }
}

// ---------------- phase 2: out[t*256+b] = dot(hs[t][b][:], w_out) + b_out ----------------
__global__ void __launch_bounds__(256) out_kernel(
    const float* __restrict__ w_out, const float* __restrict__ b_out,
    float* __restrict__ out) {
    __shared__ __align__(16) float wsm[256];
    const int tid = threadIdx.x;
    wsm[tid] = w_out[tid];
    __syncthreads();

    const int warp = tid >> 5, lane = tid & 31;
    const size_t gid = (size_t)blockIdx.x * 8 + warp;
    const float* hrow = g_hs + gid * HID;

    float s = 0.0f;
#pragma unroll
    for (int kk = 0; kk < 2; kk++) {
        int k4 = lane + 32 * kk;
        float4 h = *(const float4*)(hrow + k4 * 4);
        float4 w = *(const float4*)(wsm + k4 * 4);
        s += h.x * w.x + h.y * w.y + h.z * w.z + h.w * w.w;
    }
#pragma unroll
    for (int o = 16; o; o >>= 1) s += __shfl_down_sync(0xffffffffu, s, o);
    if (lane == 0) out[gid] = s + __ldg(b_out);
}

// ---------------- launch ----------------
extern "C" void kernel_launch(void* const* d_in, const int* in_sizes, int n_in,
                              void* d_out, int out_size) {
    const float* x     = (const float*)d_in[0];
    const float* w_ih  = (const float*)d_in[1];
    const float* w_hh  = (const float*)d_in[2];
    const float* b_ih  = (const float*)d_in[3];
    const float* b_hh  = (const float*)d_in[4];
    const float* w_out = (const float*)d_in[5];
    const float* b_out = (const float*)d_in[6];
    float* out = (float*)d_out;

    const int smem_proj = 64 * 132 * 2 * sizeof(float);
    const int smem_rec  = (96 * 256 + 16 * HSTRIDE + 96 * RPITCH) * sizeof(float);
    cudaFuncSetAttribute(input_proj_kernel,
        cudaFuncAttributeMaxDynamicSharedMemorySize, smem_proj);
    cudaFuncSetAttribute(gru_rec_kernel,
        cudaFuncAttributeMaxDynamicSharedMemorySize, smem_rec);

    input_proj_kernel<<<dim3(512, 6, 2), 256, smem_proj>>>(x, w_ih, b_ih);
    for (int c = 0; c < T_STEPS / CHUNK; c++)
        gru_rec_kernel<<<dim3(NJT, NGRP), 256, smem_rec>>>(w_hh, b_hh, c);
    out_kernel<<<16384, 256>>>(w_out, b_out, out);
}

// round 16
// speedup vs baseline: 1.7204x; 1.7204x over previous
#include <cuda_runtime.h>
#include <cstdint>

#define T_STEPS 512
#define BATCH   256
#define HID     256
#define G3      768   // 3*HID

#define J_TILE  32    // hidden units per block (96 gate rows)
#define B_TILE  16    // batch rows per group
#define NGRP    16    // batch groups
#define NJT     8     // j-tiles per group
#define CHUNK   64    // steps per launch

// ---------------- static scratch (no allocations allowed) ----------------
__device__ float    g_gi[(size_t)T_STEPS * G3 * BATCH];    // [t][g][b]
__device__ float    g_hs[(size_t)T_STEPS * BATCH * HID];   // [t][b][j]
__device__ unsigned g_flag[NGRP][NJT][32];                 // per-producer flags, 128B apart

// ---------------- helpers ----------------
__device__ __forceinline__ void ffma2(unsigned long long& d,
                                      unsigned long long a,
                                      unsigned long long b) {
    asm("fma.rn.f32x2 %0, %1, %2, %0;" : "+l"(d) : "l"(a), "l"(b));
}
__device__ __forceinline__ unsigned long long pk2(float s) {
    unsigned long long d;
    asm("mov.b64 %0, {%1,%1};" : "=l"(d) : "f"(s));
    return d;
}
__device__ __forceinline__ float2 upk(unsigned long long v) {
    float2 f;
    asm("mov.b64 {%0,%1}, %2;" : "=f"(f.x), "=f"(f.y) : "l"(v));
    return f;
}
__device__ __forceinline__ float sigm(float x) {
    return 1.0f / (1.0f + __expf(-x));
}
__device__ __forceinline__ float fast_tanh(float x) {
    float e = __expf(2.0f * x);
    return 1.0f - __fdividef(2.0f, e + 1.0f);
}

// ---------------- reset flags ----------------
__global__ void reset_kernel() {
    for (int i = threadIdx.x; i < NGRP * NJT * 32; i += 256)
        ((unsigned*)g_flag)[i] = 0u;
}

// ---------------- phase 0: gi[t][g][b] = sum_i w_ih[g][i]*x[b][t][i] + b_ih[g] ----------------
__global__ void __launch_bounds__(256) input_proj_kernel(
    const float* __restrict__ x, const float* __restrict__ w_ih,
    const float* __restrict__ b_ih) {
    extern __shared__ float sm[];
    float* wsm = sm;              // wsm[i*132 + g_local]
    float* xsm = sm + 64 * 132;   // xsm[i*132 + b_local]

    const int t  = blockIdx.x;
    const int g0 = blockIdx.y * 128;
    const int b0 = blockIdx.z * 128;
    const int tid = threadIdx.x;

#pragma unroll
    for (int it = 0; it < 8; it++) {
        int f  = tid + 256 * it;
        int gg = f >> 4, i4 = f & 15;
        float4 v = *(const float4*)(w_ih + (size_t)(g0 + gg) * 64 + i4 * 4);
        wsm[(i4 * 4 + 0) * 132 + gg] = v.x;
        wsm[(i4 * 4 + 1) * 132 + gg] = v.y;
        wsm[(i4 * 4 + 2) * 132 + gg] = v.z;
        wsm[(i4 * 4 + 3) * 132 + gg] = v.w;
    }
#pragma unroll
    for (int it = 0; it < 8; it++) {
        int f  = tid + 256 * it;
        int bb = f >> 4, i4 = f & 15;
        float4 v = *(const float4*)(x + ((size_t)(b0 + bb) * T_STEPS + t) * 64 + i4 * 4);
        xsm[(i4 * 4 + 0) * 132 + bb] = v.x;
        xsm[(i4 * 4 + 1) * 132 + bb] = v.y;
        xsm[(i4 * 4 + 2) * 132 + bb] = v.z;
        xsm[(i4 * 4 + 3) * 132 + bb] = v.w;
    }
    __syncthreads();

    const int tg = tid & 15, tb = tid >> 4;
    const int gl = tg * 8, bl = tb * 8;

    unsigned long long acc[32];
#pragma unroll
    for (int i = 0; i < 32; i++) acc[i] = 0ULL;

#pragma unroll 2
    for (int k = 0; k < 64; k++) {
        float4 wa = *(const float4*)(wsm + k * 132 + gl);
        float4 wb = *(const float4*)(wsm + k * 132 + gl + 4);
        ulonglong2 x01 = *(const ulonglong2*)(xsm + k * 132 + bl);
        ulonglong2 x23 = *(const ulonglong2*)(xsm + k * 132 + bl + 4);
        float wr[8] = {wa.x, wa.y, wa.z, wa.w, wb.x, wb.y, wb.z, wb.w};
#pragma unroll
        for (int gg = 0; gg < 8; gg++) {
            unsigned long long wd = pk2(wr[gg]);
            ffma2(acc[gg * 4 + 0], wd, x01.x);
            ffma2(acc[gg * 4 + 1], wd, x01.y);
            ffma2(acc[gg * 4 + 2], wd, x23.x);
            ffma2(acc[gg * 4 + 3], wd, x23.y);
        }
    }

#pragma unroll
    for (int gg = 0; gg < 8; gg++) {
        float bias = __ldg(b_ih + g0 + gl + gg);
        float2 p0 = upk(acc[gg * 4 + 0]);
        float2 p1 = upk(acc[gg * 4 + 1]);
        float2 p2 = upk(acc[gg * 4 + 2]);
        float2 p3 = upk(acc[gg * 4 + 3]);
        float* o = g_gi + ((size_t)t * G3 + (g0 + gl + gg)) * BATCH + b0 + bl;
        *(float4*)o       = make_float4(p0.x + bias, p0.y + bias, p1.x + bias, p1.y + bias);
        *(float4*)(o + 4) = make_float4(p2.x + bias, p2.y + bias, p3.x + bias, p3.y + bias);
    }
}

// ---------------- phase 1: GRU recurrence, per-producer flags + slice fills ----------------
// grid (8 jt, 16 grp), block 256 = (rg 0..15)x(bg 0..1)x(kc 0..7). NO cluster.
// Block: j-tile 32 (96 gate rows), batch tile 16. Data via L2 (g_hs).
// Exchange: producer stores h slice + red.release OWN flag. Consumer:
// 7 warps each poll ONE producer flag and fill ONE 32-col slice (concurrent);
// own slice written straight into h_s by combine (no L2 trip).
#define HSTRIDE 260
#define RPITCH  20

__global__ void __launch_bounds__(256) gru_rec_kernel(
    const float* __restrict__ w_hh, const float* __restrict__ b_hh,
    int chunk) {
    extern __shared__ float sm[];
    float* w_il  = sm;                       // [96][256]   96 KB
    float* h_s   = sm + 96 * 256;            // [16][260]   16.6 KB
    float* red_s = h_s + 16 * HSTRIDE;       // [96][20]    7.5 KB

    const int tid = threadIdx.x;
    const int rg  = tid >> 4;                // 0..15 row group (6 rows)
    const int bg  = (tid >> 3) & 1;          // batch parity
    const int kc  = tid & 7;                 // k chunk
    const int jt  = blockIdx.x;              // 0..7
    const int grp = blockIdx.y;              // 0..15
    const int b0  = grp * B_TILE;
    const int j0  = jt * J_TILE;
    const int warp = tid >> 5, lane = tid & 31;

    // ---- preload weights: w_il[row][k], row = jloc*3 + gate (96 rows) ----
#pragma unroll
    for (int it = 0; it < 24; it++) {
        int f4 = tid + 256 * it;             // 0..6143 float4 slots
        int row = f4 >> 6, k4 = f4 & 63;
        int jloc = row / 3, g = row - 3 * jloc;
        float4 v = __ldg((const float4*)(w_hh +
                     ((size_t)(g * 256 + j0 + jloc)) * 256 + k4 * 4));
        *(float4*)(w_il + row * 256 + k4 * 4) = v;
    }
    __syncthreads();

    // combine-role constants (tid < 128): jloc = tid&31, bq = tid>>5 (0..3)
    const int c_jl = tid & 31;
    const int c_bq = tid >> 5;
    const int c_j  = j0 + c_jl;
    const int qq   = c_jl >> 2;              // 4x4 transpose group
    const int rr   = c_jl & 3;
    float br = 0.f, bz = 0.f, bn = 0.f;
    if (tid < 128) {
        br = __ldg(b_hh + c_j);
        bz = __ldg(b_hh + 256 + c_j);
        bn = __ldg(b_hh + 512 + c_j);
    }

    const int frow = tid & 15;               // full fill: batch row
    const int fq   = tid >> 4;               // full fill: 4-float4 group (0..15)

    const int t0 = chunk * CHUNK;

    // prefetch gi(t0)
    float4 gir, giz, gin;
    if (tid < 128) {
        const float* giB = g_gi + (size_t)t0 * G3 * BATCH;
        gir = __ldcs((const float4*)(giB + (size_t)c_j * BATCH + b0 + 4 * c_bq));
        giz = __ldcs((const float4*)(giB + (size_t)(256 + c_j) * BATCH + b0 + 4 * c_bq));
        gin = __ldcs((const float4*)(giB + (size_t)(512 + c_j) * BATCH + b0 + 4 * c_bq));
    }

    const float* wrow = w_il + (6 * rg) * 256;

    for (int tl = 0; tl < CHUNK; tl++) {
        const int t = t0 + tl;

        if (t > 0) {
            if (tl == 0) {
                // ---- chunk entry: full fill from g_hs[t-1] (kernel boundary = sync) ----
                const float4* src = (const float4*)(g_hs +
                                    ((size_t)(t - 1) * BATCH + b0 + frow) * HID) + fq * 4;
                float4 v[4];
#pragma unroll
                for (int kk = 0; kk < 4; kk++) v[kk] = __ldcg(src + kk);
#pragma unroll
                for (int kk = 0; kk < 4; kk++)
                    *(float4*)(h_s + frow * HSTRIDE + fq * 16 + kk * 4) = v[kk];
            } else if (warp >= 1) {
                // ---- steady state: warp w handles slice s = (jt+w)&7 ----
                const int s = (jt + warp) & 7;
                if (lane == 0) {
                    const unsigned* fl = &g_flag[grp][s][0];
                    unsigned v;
                    do {
                        asm volatile("ld.acquire.gpu.global.u32 %0, [%1];"
                                     : "=r"(v) : "l"(fl) : "memory");
                    } while (v < (unsigned)t);
                }
                __syncwarp();
                const int r = lane & 15, hf = lane >> 4;
                const float4* src = (const float4*)(g_hs +
                                    ((size_t)(t - 1) * BATCH + b0 + r) * HID + 32 * s + 16 * hf);
                float4 v0 = __ldcg(src + 0);
                float4 v1 = __ldcg(src + 1);
                float4 v2 = __ldcg(src + 2);
                float4 v3 = __ldcg(src + 3);
                float* dst = h_s + r * HSTRIDE + 32 * s + 16 * hf;
                *(float4*)(dst + 0)  = v0;
                *(float4*)(dst + 4)  = v1;
                *(float4*)(dst + 8)  = v2;
                *(float4*)(dst + 12) = v3;
            }
            __syncthreads();

            // ---- GEMM: 6 rows x 8 batches x 32 k per thread ----
            unsigned long long acc[6][8];
#pragma unroll
            for (int r = 0; r < 6; r++)
#pragma unroll
                for (int m = 0; m < 8; m++) acc[r][m] = 0ULL;

#pragma unroll
            for (int i = 0; i < 8; i++) {
                const int k4 = kc + 8 * i;
                ulonglong2 wv[6];
#pragma unroll
                for (int r = 0; r < 6; r++)
                    wv[r] = *(const ulonglong2*)(wrow + r * 256 + k4 * 4);
#pragma unroll
                for (int m = 0; m < 8; m++) {
                    ulonglong2 hv = *(const ulonglong2*)
                        (h_s + (2 * m + bg) * HSTRIDE + k4 * 4);
#pragma unroll
                    for (int r = 0; r < 6; r++) {
                        ffma2(acc[r][m], wv[r].x, hv.x);
                        ffma2(acc[r][m], wv[r].y, hv.y);
                    }
                }
            }

            // ---- fold f32x2 + butterfly kc-reduction with redistribution ----
            float s0[6][8];
#pragma unroll
            for (int r = 0; r < 6; r++)
#pragma unroll
                for (int m = 0; m < 8; m++) {
                    float2 p = upk(acc[r][m]);
                    s0[r][m] = p.x + p.y;
                }
            float s1[6][4];
            {
                bool hi = kc & 1;
#pragma unroll
                for (int r = 0; r < 6; r++)
#pragma unroll
                    for (int q = 0; q < 4; q++) {
                        float mine   = hi ? s0[r][2 * q + 1] : s0[r][2 * q];
                        float theirs = hi ? s0[r][2 * q]     : s0[r][2 * q + 1];
                        s1[r][q] = mine + __shfl_xor_sync(0xffffffffu, theirs, 1);
                    }
            }
            float s1b[6][2];
            {
                bool hi = (kc >> 1) & 1;
#pragma unroll
                for (int r = 0; r < 6; r++)
#pragma unroll
                    for (int q = 0; q < 2; q++) {
                        float mine   = hi ? s1[r][2 * q + 1] : s1[r][2 * q];
                        float theirs = hi ? s1[r][2 * q]     : s1[r][2 * q + 1];
                        s1b[r][q] = mine + __shfl_xor_sync(0xffffffffu, theirs, 2);
                    }
            }
            float s2[6];
            {
                bool hi = (kc >> 2) & 1;
#pragma unroll
                for (int r = 0; r < 6; r++) {
                    float mine   = hi ? s1b[r][1] : s1b[r][0];
                    float theirs = hi ? s1b[r][0] : s1b[r][1];
                    s2[r] = mine + __shfl_xor_sync(0xffffffffu, theirs, 4);
                }
            }
            // handoff: red_s[row][bb], bb = 2*kc + bg
            float* rs = red_s + (2 * kc + bg);
#pragma unroll
            for (int r = 0; r < 6; r++)
                rs[(6 * rg + r) * RPITCH] = s2[r];
            __syncthreads();
        }

        // ---- combine (tid < 128): 1 j x 4 batches each ----
        if (tid < 128) {
            float4 sR = make_float4(0.f, 0.f, 0.f, 0.f);
            float4 sZ = sR, sN = sR;
            if (t > 0) {
                sR = *(const float4*)(red_s + (3 * c_jl + 0) * RPITCH + 4 * c_bq);
                sZ = *(const float4*)(red_s + (3 * c_jl + 1) * RPITCH + 4 * c_bq);
                sN = *(const float4*)(red_s + (3 * c_jl + 2) * RPITCH + 4 * c_bq);
            }
            float sRa[4] = {sR.x, sR.y, sR.z, sR.w};
            float sZa[4] = {sZ.x, sZ.y, sZ.z, sZ.w};
            float sNa[4] = {sN.x, sN.y, sN.z, sN.w};
            float giRv[4] = {gir.x, gir.y, gir.z, gir.w};
            float giZv[4] = {giz.x, giz.y, giz.z, giz.w};
            float giNv[4] = {gin.x, gin.y, gin.z, gin.w};

            float hnew[4];
#pragma unroll
            for (int m = 0; m < 4; m++) {
                float rgt = sigm(giRv[m] + sRa[m] + br);
                float zg = sigm(giZv[m] + sZa[m] + bz);
                float ng = fast_tanh(giNv[m] + rgt * (sNa[m] + bn));
                float hp_ = (t == 0) ? 0.0f
                          : h_s[(4 * c_bq + m) * HSTRIDE + c_j];
                hnew[m] = (1.0f - zg) * ng + zg * hp_;
            }

            // ---- 4x4 transpose within lane quads ----
            float T[4];
#pragma unroll
            for (int d = 0; d < 4; d++) {
                int gidx = (rr + d) & 3;
                float sv = hnew[(rr - d) & 3];
                float rv = __shfl_sync(0xffffffffu, sv, (lane & 28) | gidx);
                T[gidx] = rv;
            }

            // own-slice straight into h_s for next step (row = 4*c_bq+rr, cols j0+4qq..)
            *(float4*)(h_s + (4 * c_bq + rr) * HSTRIDE + j0 + 4 * qq) =
                make_float4(T[0], T[1], T[2], T[3]);

            // history/exchange store: one 16B store to L2
            float* hsT = g_hs + ((size_t)t * BATCH + b0 + 4 * c_bq + rr) * HID;
            __stcg((float4*)(hsT + j0 + 4 * qq),
                   make_float4(T[0], T[1], T[2], T[3]));
            __threadfence();
        }

        // ---- publish own flag, then prefetch next gi ----
        __syncthreads();
        if (tid == 0)
            asm volatile("red.release.gpu.global.add.u32 [%0], %1;"
                         :: "l"(&g_flag[grp][jt][0]), "r"(1u) : "memory");

        if (tl + 1 < CHUNK && tid < 128) {
            const float* giN = g_gi + (size_t)(t + 1) * G3 * BATCH;
            gir = __ldcs((const float4*)(giN + (size_t)c_j * BATCH + b0 + 4 * c_bq));
            giz = __ldcs((const float4*)(giN + (size_t)(256 + c_j) * BATCH + b0 + 4 * c_bq));
            gin = __ldcs((const float4*)(giN + (size_t)(512 + c_j) * BATCH + b0 + 4 * c_bq));
        }
    }
}

// ---------------- phase 2: out[t*256+b] = dot(hs[t][b][:], w_out) + b_out ----------------
__global__ void __launch_bounds__(256) out_kernel(
    const float* __restrict__ w_out, const float* __restrict__ b_out,
    float* __restrict__ out) {
    __shared__ __align__(16) float wsm[256];
    const int tid = threadIdx.x;
    wsm[tid] = w_out[tid];
    __syncthreads();

    const int warp = tid >> 5, lane = tid & 31;
    const size_t gid = (size_t)blockIdx.x * 8 + warp;
    const float* hrow = g_hs + gid * HID;

    float s = 0.0f;
#pragma unroll
    for (int kk = 0; kk < 2; kk++) {
        int k4 = lane + 32 * kk;
        float4 h = *(const float4*)(hrow + k4 * 4);
        float4 w = *(const float4*)(wsm + k4 * 4);
        s += h.x * w.x + h.y * w.y + h.z * w.z + h.w * w.w;
    }
#pragma unroll
    for (int o = 16; o; o >>= 1) s += __shfl_down_sync(0xffffffffu, s, o);
    if (lane == 0) out[gid] = s + __ldg(b_out);
}

// ---------------- launch ----------------
extern "C" void kernel_launch(void* const* d_in, const int* in_sizes, int n_in,
                              void* d_out, int out_size) {
    const float* x     = (const float*)d_in[0];
    const float* w_ih  = (const float*)d_in[1];
    const float* w_hh  = (const float*)d_in[2];
    const float* b_ih  = (const float*)d_in[3];
    const float* b_hh  = (const float*)d_in[4];
    const float* w_out = (const float*)d_in[5];
    const float* b_out = (const float*)d_in[6];
    float* out = (float*)d_out;

    const int smem_proj = 64 * 132 * 2 * sizeof(float);
    const int smem_rec  = (96 * 256 + 16 * HSTRIDE + 96 * RPITCH) * sizeof(float);
    cudaFuncSetAttribute(input_proj_kernel,
        cudaFuncAttributeMaxDynamicSharedMemorySize, smem_proj);
    cudaFuncSetAttribute(gru_rec_kernel,
        cudaFuncAttributeMaxDynamicSharedMemorySize, smem_rec);

    reset_kernel<<<1, 256>>>();
    input_proj_kernel<<<dim3(512, 6, 2), 256, smem_proj>>>(x, w_ih, b_ih);
    for (int c = 0; c < T_STEPS / CHUNK; c++)
        gru_rec_kernel<<<dim3(NJT, NGRP), 256, smem_rec>>>(w_hh, b_hh, c);
    out_kernel<<<16384, 256>>>(w_out, b_out, out);
}